// round 10
// baseline (speedup 1.0000x reference)
#include <cuda_runtime.h>
#include <math_constants.h>

#define S    8        // slices per row
#define K1T  256      // threads for slice kernels
#define NT   1024     // threads for per-row kernels
#define NC   8192     // candidate capacity per row
#define HB   2048     // histogram bins over [-16,16), width 1/64 (raw logits)
#define BMAX 256      // max batch rows supported

// -------- global scratch (static __device__, allocation-free) --------
__device__ int   g_hist[BMAX * S * HB];
__device__ float g_pmax[BMAX * S];
__device__ float g_Ml[BMAX];
__device__ int   g_bcut[BMAX];
__device__ int   g_cnt[BMAX];
__device__ float g_val[BMAX * NC];
__device__ int   g_idx[BMAX * NC];

// order-preserving float<->uint (ascending)
__device__ __forceinline__ unsigned f2o(float f) {
    unsigned u = __float_as_uint(f);
    return u ^ ((u & 0x80000000u) ? 0xFFFFFFFFu : 0x80000000u);
}
__device__ __forceinline__ int binraw(float l) {
    float t = (l + 16.0f) * 64.0f;
    int b = (int)t;
    if (t < 0.f) b = 0;
    if (b > HB - 1) b = HB - 1;
    return b;
}

// ==================== K1: per-slice histogram + max ====================
__global__ __launch_bounds__(K1T)
void k_hist(const float* __restrict__ logits, int V)
{
    __shared__ int h[HB];
    __shared__ float wmax[K1T / 32];
    const int row = blockIdx.x / S, sl = blockIdx.x - row * S;
    const float* lg = logits + (size_t)row * V;
    const int per = V / S;
    const int beg = sl * per, end = (sl == S - 1) ? V : beg + per;
    const int tid = threadIdx.x;

    for (int b = tid; b < HB; b += K1T) h[b] = 0;
    __syncthreads();

    float mx = -CUDART_INF_F;
    const int beg_al = (beg + 3) & ~3, end_al = end & ~3;
    for (int i = beg + tid; i < beg_al && i < end; i += K1T) {
        float l = lg[i]; mx = fmaxf(mx, l); atomicAdd(&h[binraw(l)], 1);
    }
    const float4* lg4 = (const float4*)lg;
    for (int i = beg_al / 4 + tid; i < end_al / 4; i += K1T) {
        float4 v = lg4[i];
        mx = fmaxf(mx, fmaxf(fmaxf(v.x, v.y), fmaxf(v.z, v.w)));
        atomicAdd(&h[binraw(v.x)], 1); atomicAdd(&h[binraw(v.y)], 1);
        atomicAdd(&h[binraw(v.z)], 1); atomicAdd(&h[binraw(v.w)], 1);
    }
    for (int i = end_al + tid; i < end; i += K1T) {
        float l = lg[i]; mx = fmaxf(mx, l); atomicAdd(&h[binraw(l)], 1);
    }

    #pragma unroll
    for (int o = 16; o; o >>= 1) mx = fmaxf(mx, __shfl_xor_sync(0xFFFFFFFFu, mx, o));
    if ((tid & 31) == 0) wmax[tid >> 5] = mx;
    __syncthreads();
    if (tid == 0) {
        float m = wmax[0];
        #pragma unroll
        for (int w = 1; w < K1T / 32; ++w) m = fmaxf(m, wmax[w]);
        g_pmax[row * S + sl] = m;
    }
    int* gh = g_hist + (size_t)(row * S + sl) * HB;
    for (int b = tid; b < HB; b += K1T) gh[b] = h[b];
}

// ============ K2: merge hists, suffix scan, bcut + Ml + zero cnt ============
__global__ __launch_bounds__(NT)
void k_merge(const int* __restrict__ topks, int V)
{
    __shared__ int sa[HB];
    __shared__ int sb[HB];
    __shared__ int s_bcut;
    const int row = blockIdx.x, tid = threadIdx.x;
    int k = topks[row]; if (k < 1) k = 1; if (k > V) k = V;

    for (int b = tid; b < HB; b += NT) {
        int s = 0;
        #pragma unroll
        for (int s2 = 0; s2 < S; ++s2) s += g_hist[(size_t)(row * S + s2) * HB + b];
        sa[b] = s;
    }
    __syncthreads();
    int* ia = sa; int* ib = sb;
    for (int d = 1; d < HB; d <<= 1) {
        for (int b = tid; b < HB; b += NT)
            ib[b] = ia[b] + ((b + d < HB) ? ia[b + d] : 0);
        __syncthreads();
        int* t = ia; ia = ib; ib = t;
    }
    for (int b = tid; b < HB; b += NT) {
        int s = ia[b];
        int nx = (b == HB - 1) ? 0 : ia[b + 1];
        if (s >= k && nx < k) s_bcut = b;
    }
    __syncthreads();
    if (tid == 0) {
        float mx = g_pmax[row * S];
        #pragma unroll
        for (int s2 = 1; s2 < S; ++s2) mx = fmaxf(mx, g_pmax[row * S + s2]);
        g_Ml[row]   = mx;
        g_bcut[row] = s_bcut;
        g_cnt[row]  = 0;
    }
}

// ============== K3: per-slice gather of bin >= bcut candidates ==============
__global__ __launch_bounds__(K1T)
void k_gather(const float* __restrict__ logits, const float* __restrict__ temps, int V)
{
    const int row = blockIdx.x / S, sl = blockIdx.x - row * S;
    const float* lg = logits + (size_t)row * V;
    const float T = temps[row];
    const int bcut = g_bcut[row];
    float* gv = g_val + (size_t)row * NC;
    int*   gi = g_idx + (size_t)row * NC;
    const int per = V / S;
    const int beg = sl * per, end = (sl == S - 1) ? V : beg + per;
    const int tid = threadIdx.x;
    const int lane = tid & 31;
    const unsigned lml = (1u << lane) - 1u;

    const int beg_al = (beg + 3) & ~3, end_al = end & ~3;
    for (int i = beg + tid; i < beg_al && i < end; i += K1T) {
        float l = lg[i];
        if (binraw(l) >= bcut) {
            int pos = atomicAdd(&g_cnt[row], 1);
            if (pos < NC) { gv[pos] = __fdiv_rn(l, T); gi[pos] = i; }
        }
    }
    const float4* lg4 = (const float4*)lg;
    const int v0 = beg_al / 4, v1 = end_al / 4;
    const int nv = v1 - v0;
    const int iters = (nv + K1T - 1) / K1T;
    for (int it = 0; it < iters; ++it) {
        int i = v0 + it * K1T + tid;
        bool in = i < v1;
        float4 v = in ? lg4[i] : make_float4(-1e30f, -1e30f, -1e30f, -1e30f);
        float comp[4] = {v.x, v.y, v.z, v.w};
        #pragma unroll
        for (int c = 0; c < 4; ++c) {
            bool hit = in && (binraw(comp[c]) >= bcut);
            unsigned mask = __ballot_sync(0xFFFFFFFFu, hit);
            if (mask) {
                int leader = __ffs(mask) - 1;
                int base = 0;
                if (lane == leader) base = atomicAdd(&g_cnt[row], __popc(mask));
                base = __shfl_sync(0xFFFFFFFFu, base, leader);
                if (hit) {
                    int pos = base + __popc(mask & lml);
                    if (pos < NC) { gv[pos] = __fdiv_rn(comp[c], T); gi[pos] = (i << 2) + c; }
                }
            }
        }
    }
    for (int i = end_al + tid; i < end; i += K1T) {
        float l = lg[i];
        if (binraw(l) >= bcut) {
            int pos = atomicAdd(&g_cnt[row], 1);
            if (pos < NC) { gv[pos] = __fdiv_rn(l, T); gi[pos] = i; }
        }
    }
}

// ======== K4: selects + final sampling over candidates (R9 back end) ========
__global__ __launch_bounds__(NT)
void k_final(const float* __restrict__ temps,
             const int*   __restrict__ topks,
             const float* __restrict__ topps,
             const float* __restrict__ minps,
             const float* __restrict__ noise,
             float* __restrict__ out, int V)
{
    extern __shared__ unsigned char smem_raw[];
    float* s_val = (float*)smem_raw;       // NC
    int*   s_idx = (int*)(s_val + NC);     // NC
    __shared__ int   s_hist[256];
    __shared__ int   s_sa[256];
    __shared__ float wf[32];
    __shared__ int   sh_wi[32];
    __shared__ int   sh_sel;

    const int tid = threadIdx.x;
    const int row = blockIdx.x;
    const float* nz = noise + (size_t)row * V;
    const float T = temps[row];
    int k = topks[row]; if (k < 1) k = 1; if (k > V) k = V;
    const float p  = topps[row];
    const float mp = minps[row];
    const int lane = tid & 31;

    int n = g_cnt[row]; if (n > NC) n = NC;
    if (k > n) k = n;
    const float M = __fdiv_rn(g_Ml[row], T);

    const float* gv = g_val + (size_t)row * NC;
    const int*   gi = g_idx + (size_t)row * NC;
    for (int j = tid; j < n; j += NT) { s_val[j] = gv[j]; s_idx[j] = gi[j]; }
    __syncthreads();

    // ---- count radix-select: thrO = k-th largest (ordered uint) ----
    unsigned thrO = 0;
    {
        unsigned pref = 0;
        int krem = k;
        for (int byte = 3; byte >= 0; --byte) {
            if (tid < 256) s_hist[tid] = 0;
            __syncthreads();
            const unsigned hm = (byte == 3) ? 0u : (0xFFFFFFFFu << (8 * (byte + 1)));
            for (int j = tid; j < n; j += NT) {
                unsigned u = f2o(s_val[j]);
                if ((u & hm) == (pref & hm))
                    atomicAdd(&s_hist[(u >> (8 * byte)) & 255u], 1);
            }
            __syncthreads();
            if (tid < 32) {
                int base = tid * 8;
                int v[8]; int sum = 0;
                #pragma unroll
                for (int q = 0; q < 8; ++q) { v[q] = s_hist[base + q]; sum += v[q]; }
                int incl = sum;
                #pragma unroll
                for (int o = 1; o < 32; o <<= 1) {
                    int t = __shfl_down_sync(0xFFFFFFFFu, incl, o);
                    if (tid + o < 32) incl += t;
                }
                int run = incl - sum;
                #pragma unroll
                for (int q = 7; q >= 0; --q) { run += v[q]; s_sa[base + q] = run; }
            }
            __syncthreads();
            if (tid < 256) {
                int s = s_sa[tid];
                int nx = (tid == 255) ? 0 : s_sa[tid + 1];
                if (s >= krem && nx < krem) sh_sel = tid;
            }
            __syncthreads();
            int sel = sh_sel;
            krem -= (sel == 255) ? 0 : s_sa[sel + 1];
            pref |= (unsigned)sel << (8 * byte);
            __syncthreads();
        }
        thrO = pref;
    }

    // ---- Z1 over top-k survivors ----
    float z = 0.f;
    for (int j = tid; j < n; j += NT) {
        float x = s_val[j];
        if (f2o(x) >= thrO) z += expf(x - M);
    }
    #pragma unroll
    for (int o = 16; o; o >>= 1) z += __shfl_xor_sync(0xFFFFFFFFu, z, o);
    if (lane == 0) wf[tid >> 5] = z;
    __syncthreads();
    if (tid < 32) {
        float x = wf[tid];
        #pragma unroll
        for (int o = 16; o; o >>= 1) x += __shfl_xor_sync(0xFFFFFFFFu, x, o);
        if (tid == 0) wf[0] = x;
    }
    __syncthreads();
    const float Z1 = wf[0];
    __syncthreads();

    // ---- mass radix-select: v2O (top-p boundary value) ----
    unsigned v2O = thrO;
    {
        float* s_hf = (float*)s_hist;
        float* s_sf = (float*)s_sa;
        float tr = p * Z1;
        unsigned pref = 0;
        for (int byte = 3; byte >= 0; --byte) {
            if (tid < 256) s_hf[tid] = 0.f;
            __syncthreads();
            const unsigned hm = (byte == 3) ? 0u : (0xFFFFFFFFu << (8 * (byte + 1)));
            for (int j = tid; j < n; j += NT) {
                float x = s_val[j];
                unsigned u = f2o(x);
                if (u >= thrO && (u & hm) == (pref & hm))
                    atomicAdd(&s_hf[(u >> (8 * byte)) & 255u], expf(x - M));
            }
            __syncthreads();
            if (tid < 32) {
                int base = tid * 8;
                float v[8]; float sum = 0.f;
                #pragma unroll
                for (int q = 0; q < 8; ++q) { v[q] = s_hf[base + q]; sum += v[q]; }
                float incl = sum;
                #pragma unroll
                for (int o = 1; o < 32; o <<= 1) {
                    float t = __shfl_down_sync(0xFFFFFFFFu, incl, o);
                    if (tid + o < 32) incl += t;
                }
                float run = incl - sum;
                #pragma unroll
                for (int q = 7; q >= 0; --q) { run += v[q]; s_sf[base + q] = run; }
            }
            __syncthreads();
            float tt = fminf(tr, s_sf[0]);
            tt = fmaxf(tt, 1e-35f);
            if (tid < 256) {
                float s = s_sf[tid];
                float nx = (tid == 255) ? 0.f : s_sf[tid + 1];
                if (s >= tt && nx < tt) sh_sel = tid;
            }
            __syncthreads();
            int sel = sh_sel;
            tr = tt - ((sel == 255) ? 0.f : s_sf[sel + 1]);
            pref |= (unsigned)sel << (8 * byte);
            __syncthreads();
        }
        v2O = pref;
    }

    // ---- final argmax of exp(x-M)/max(noise,1e-10) over kept set ----
    const bool usemp = (mp > 0.f);
    float bv = -1.f; int bi = 0x7FFFFFFF;
    for (int j = tid; j < n; j += NT) {
        float x = s_val[j];
        if (f2o(x) >= v2O) {
            float e = expf(x - M);
            if (!usemp || e >= mp) {
                int ix = s_idx[j];
                float sc = __fdiv_rn(e, fmaxf(nz[ix], 1e-10f));
                if (sc > bv || (sc == bv && ix < bi)) { bv = sc; bi = ix; }
            }
        }
    }
    #pragma unroll
    for (int o = 16; o; o >>= 1) {
        float ov = __shfl_xor_sync(0xFFFFFFFFu, bv, o);
        int   oi = __shfl_xor_sync(0xFFFFFFFFu, bi, o);
        if (ov > bv || (ov == bv && oi < bi)) { bv = ov; bi = oi; }
    }
    if (lane == 0) { wf[tid >> 5] = bv; sh_wi[tid >> 5] = bi; }
    __syncthreads();
    if (tid < 32) {
        float xv = wf[tid];
        int   xi = sh_wi[tid];
        #pragma unroll
        for (int o = 16; o; o >>= 1) {
            float ov = __shfl_xor_sync(0xFFFFFFFFu, xv, o);
            int   oi = __shfl_xor_sync(0xFFFFFFFFu, xi, o);
            if (ov > xv || (ov == xv && oi < xi)) { xv = ov; xi = oi; }
        }
        if (tid == 0) out[row] = (float)xi;
    }
}

extern "C" void kernel_launch(void* const* d_in, const int* in_sizes, int n_in,
                              void* d_out, int out_size)
{
    const float* logits = (const float*)d_in[0];
    const float* temps  = (const float*)d_in[1];
    const int*   topks  = (const int*)d_in[2];
    const float* topps  = (const float*)d_in[3];
    const float* minps  = (const float*)d_in[4];
    const float* noise  = (const float*)d_in[5];
    const int B = out_size;              // output: [B] sampled indices (float32)
    const int V = in_sizes[0] / B;       // logits: [B, V]

    k_hist  <<<B * S, K1T>>>(logits, V);
    k_merge <<<B,     NT >>>(topks, V);
    k_gather<<<B * S, K1T>>>(logits, temps, V);

    const size_t smem4 = (size_t)NC * 8;
    cudaFuncSetAttribute(k_final, cudaFuncAttributeMaxDynamicSharedMemorySize, (int)smem4);
    k_final <<<B, NT, smem4>>>(temps, topks, topps, minps, noise, (float*)d_out, V);
}

// round 11
// speedup vs baseline: 1.7315x; 1.7315x over previous
#include <cuda_runtime.h>
#include <math_constants.h>

#define NT 1024      // threads per CTA (one CTA per row)
#define NC 6144      // candidate capacity
#define SP 4096      // survivor / sort / scan capacity
#define HB 2048      // histogram bins over [-16,16), width 1/64 (raw logits)

// order-preserving float<->uint (ascending)
__device__ __forceinline__ unsigned f2o(float f) {
    unsigned u = __float_as_uint(f);
    return u ^ ((u & 0x80000000u) ? 0xFFFFFFFFu : 0x80000000u);
}
__device__ __forceinline__ float o2f(unsigned u) {
    unsigned v = u ^ ((u & 0x80000000u) ? 0x80000000u : 0xFFFFFFFFu);
    return __uint_as_float(v);
}
__device__ __forceinline__ int binraw(float l) {
    float t = (l + 16.0f) * 64.0f;
    int b = (int)t;
    if (t < 0.f) b = 0;
    if (b > HB - 1) b = HB - 1;
    return b;
}

__device__ __forceinline__ float blk_max(float v, float* w, int tid) {
    #pragma unroll
    for (int o = 16; o; o >>= 1) v = fmaxf(v, __shfl_xor_sync(0xFFFFFFFFu, v, o));
    if ((tid & 31) == 0) w[tid >> 5] = v;
    __syncthreads();
    if (tid < 32) {
        float x = (tid < NT / 32) ? w[tid] : -CUDART_INF_F;
        #pragma unroll
        for (int o = 16; o; o >>= 1) x = fmaxf(x, __shfl_xor_sync(0xFFFFFFFFu, x, o));
        if (tid == 0) w[0] = x;
    }
    __syncthreads();
    float r = w[0];
    __syncthreads();
    return r;
}
__device__ __forceinline__ float blk_sumf(float v, float* w, int tid) {
    #pragma unroll
    for (int o = 16; o; o >>= 1) v += __shfl_xor_sync(0xFFFFFFFFu, v, o);
    if ((tid & 31) == 0) w[tid >> 5] = v;
    __syncthreads();
    if (tid < 32) {
        float x = (tid < NT / 32) ? w[tid] : 0.f;
        #pragma unroll
        for (int o = 16; o; o >>= 1) x += __shfl_xor_sync(0xFFFFFFFFu, x, o);
        if (tid == 0) w[0] = x;
    }
    __syncthreads();
    float r = w[0];
    __syncthreads();
    return r;
}
__device__ __forceinline__ int blk_sumi(int v, int* w, int tid) {
    #pragma unroll
    for (int o = 16; o; o >>= 1) v += __shfl_xor_sync(0xFFFFFFFFu, v, o);
    if ((tid & 31) == 0) w[tid >> 5] = v;
    __syncthreads();
    if (tid < 32) {
        int x = (tid < NT / 32) ? w[tid] : 0;
        #pragma unroll
        for (int o = 16; o; o >>= 1) x += __shfl_xor_sync(0xFFFFFFFFu, x, o);
        if (tid == 0) w[0] = x;
    }
    __syncthreads();
    int r = w[0];
    __syncthreads();
    return r;
}

__global__ __launch_bounds__(NT, 1)
void sampler_kernel(const float* __restrict__ logits,
                    const float* __restrict__ temps,
                    const int*   __restrict__ topks,
                    const float* __restrict__ topps,
                    const float* __restrict__ minps,
                    const float* __restrict__ noise,
                    float* __restrict__ out, int V)
{
    extern __shared__ unsigned char smem_raw[];
    float* s_val  = (float*)smem_raw;            // NC candidate values x = l/T
    int*   s_idx  = (int*)(s_val + NC);          // NC candidate indices
    float* s_sv   = (float*)(s_idx + NC);        // SP survivor values
    int*   s_si   = (int*)(s_sv + SP);           // SP survivor indices
    float* s_a    = (float*)(s_si + SP);         // SP scan ping (also int scratch)
    float* s_b    = s_a + SP;                    // SP scan pong
    int*   s_hist = (int*)(s_b + SP);            // HB histogram / 256 radix bins

    __shared__ float wf[32];
    __shared__ int   wi[32];
    __shared__ int   sh_cnt, sh_bcut, sh_sel;

    const int tid = threadIdx.x;
    const int row = blockIdx.x;
    const float* lg = logits + (size_t)row * V;
    const float* nz = noise  + (size_t)row * V;
    const float T = temps[row];
    int k = topks[row]; if (k < 1) k = 1; if (k > V) k = V;
    const float p  = topps[row];
    const float mp = minps[row];
    const int lane = tid & 31;
    const unsigned lml = (1u << lane) - 1u;

    // ------- pass 0: fused max + histogram of RAW logits (no divisions) -------
    for (int b = tid; b < HB; b += NT) s_hist[b] = 0;
    __syncthreads();

    float lmax = -CUDART_INF_F;
    const float4* lg4 = (const float4*)lg;
    const int V4 = V >> 2;
    for (int i = tid; i < V4; i += NT) {
        float4 v = lg4[i];
        lmax = fmaxf(lmax, fmaxf(fmaxf(v.x, v.y), fmaxf(v.z, v.w)));
        atomicAdd(&s_hist[binraw(v.x)], 1);
        atomicAdd(&s_hist[binraw(v.y)], 1);
        atomicAdd(&s_hist[binraw(v.z)], 1);
        atomicAdd(&s_hist[binraw(v.w)], 1);
    }
    for (int i = (V4 << 2) + tid; i < V; i += NT) {     // tail (V%4)
        float l = lg[i];
        lmax = fmaxf(lmax, l);
        atomicAdd(&s_hist[binraw(l)], 1);
    }
    const float Ml = blk_max(lmax, wf, tid);
    const float M  = __fdiv_rn(Ml, T);   // == max of divided values (monotone div)

    // ------- suffix-sum histogram, pick cutoff bin with cum >= k -------
    {
        int* ia = (int*)s_a; int* ib = (int*)s_b;
        for (int b = tid; b < HB; b += NT) ia[b] = s_hist[b];
        __syncthreads();
        for (int d = 1; d < HB; d <<= 1) {
            for (int b = tid; b < HB; b += NT)
                ib[b] = ia[b] + ((b + d < HB) ? ia[b + d] : 0);
            __syncthreads();
            int* t = ia; ia = ib; ib = t;
        }
        for (int b = tid; b < HB; b += NT) {
            int s = ia[b];
            int snext = (b == HB - 1) ? 0 : ia[b + 1];
            if (s >= k && snext < k) sh_bcut = b;
        }
        __syncthreads();
    }
    const int bcut = sh_bcut;

    // ------- gather pass: compact raw-bin >= bcut, store x = l/T -------
    if (tid == 0) sh_cnt = 0;
    __syncthreads();
    {
        const int iters = (V4 + NT - 1) / NT;
        for (int it = 0; it < iters; ++it) {
            int i = tid + it * NT;
            bool in = (i < V4);
            float4 v = in ? lg4[i] : make_float4(-1e30f, -1e30f, -1e30f, -1e30f);
            float comp[4] = {v.x, v.y, v.z, v.w};
            #pragma unroll
            for (int c = 0; c < 4; ++c) {
                bool hit = in && (binraw(comp[c]) >= bcut);
                unsigned mask = __ballot_sync(0xFFFFFFFFu, hit);
                if (mask) {
                    int leader = __ffs(mask) - 1;
                    int base = 0;
                    if (lane == leader) base = atomicAdd(&sh_cnt, __popc(mask));
                    base = __shfl_sync(0xFFFFFFFFu, base, leader);
                    if (hit) {
                        int pos = base + __popc(mask & lml);
                        if (pos < NC) { s_val[pos] = __fdiv_rn(comp[c], T); s_idx[pos] = (i << 2) + c; }
                    }
                }
            }
        }
        for (int i = (V4 << 2) + tid; i < V; i += NT) {   // tail
            float l = lg[i];
            if (binraw(l) >= bcut) {
                int pos = atomicAdd(&sh_cnt, 1);
                if (pos < NC) { s_val[pos] = __fdiv_rn(l, T); s_idx[pos] = i; }
            }
        }
    }
    __syncthreads();
    int n = sh_cnt; if (n > NC) n = NC;
    if (k > n) k = n;
    __syncthreads();

    // ------- exact k-th largest via 4-pass radix select (on divided values) ------
    unsigned prefix = 0;
    int krem = k;
    for (int byte = 3; byte >= 0; --byte) {
        for (int b = tid; b < 256; b += NT) s_hist[b] = 0;
        __syncthreads();
        const unsigned hmask = (byte == 3) ? 0u : (0xFFFFFFFFu << (8 * (byte + 1)));
        for (int j = tid; j < n; j += NT) {
            unsigned u = f2o(s_val[j]);
            if ((u & hmask) == (prefix & hmask))
                atomicAdd(&s_hist[(u >> (8 * byte)) & 255], 1);
        }
        __syncthreads();
        // suffix-sum of 256 bins
        int* ia = (int*)s_a; int* ib = (int*)s_b;
        if (tid < 256) ia[tid] = s_hist[tid];
        __syncthreads();
        for (int d = 1; d < 256; d <<= 1) {
            if (tid < 256) ib[tid] = ia[tid] + ((tid + d < 256) ? ia[tid + d] : 0);
            __syncthreads();
            int* t = ia; ia = ib; ib = t;
        }
        if (tid < 256) {
            int s = ia[tid];
            int snext = (tid == 255) ? 0 : ia[tid + 1];
            if (s >= krem && snext < krem) sh_sel = tid;
        }
        __syncthreads();
        int sel = sh_sel;
        int higher = (sel == 255) ? 0 : ia[sel + 1];
        krem -= higher;
        prefix |= (unsigned)sel << (8 * byte);
        __syncthreads();
    }
    const float thr = o2f(prefix);

    // ------- compact survivors (v >= thr), count m -------
    if (tid == 0) sh_cnt = 0;
    __syncthreads();
    {
        const int iters = (n + NT - 1) / NT;
        for (int it = 0; it < iters; ++it) {
            int j = tid + it * NT;
            bool hit = (j < n) && (s_val[j] >= thr);
            unsigned mask = __ballot_sync(0xFFFFFFFFu, hit);
            if (mask) {
                int leader = __ffs(mask) - 1;
                int base = 0;
                if (lane == leader) base = atomicAdd(&sh_cnt, __popc(mask));
                base = __shfl_sync(0xFFFFFFFFu, base, leader);
                if (hit) {
                    int pos = base + __popc(mask & lml);
                    if (pos < SP) { s_sv[pos] = s_val[j]; s_si[pos] = s_idx[j]; }
                }
            }
        }
    }
    __syncthreads();
    int m = sh_cnt; if (m > SP) m = SP;
    __syncthreads();

    // ------- sort survivors desc by (value, index-desc) -------
    int NP = 1; while (NP < m) NP <<= 1;
    for (int j = m + tid; j < NP; j += NT) { s_sv[j] = -CUDART_INF_F; s_si[j] = -1; }
    __syncthreads();
    for (int size = 2; size <= NP; size <<= 1)
        for (int st = size >> 1; st; st >>= 1) {
            for (int pp = tid; pp < (NP >> 1); pp += NT) {
                int low = pp & (st - 1);
                int i = ((pp ^ low) << 1) | low;
                int l = i + st;
                float vi = s_sv[i], vl = s_sv[l];
                int   ii = s_si[i], il = s_si[l];
                bool dir = ((i & size) == 0);
                bool sw  = (vl > vi) || (vl == vi && il > ii);
                if (sw == dir) { s_sv[i] = vl; s_sv[l] = vi; s_si[i] = il; s_si[l] = ii; }
            }
            __syncthreads();
        }

    // ------- softmax sum over survivors -------
    float z = 0.f;
    for (int j = tid; j < m; j += NT) z += expf(s_sv[j] - M);
    const float Z1 = blk_sumf(z, wf, tid);

    // probs (desc order) + inclusive suffix scan == reference ascending cumsum
    for (int j = tid; j < NP; j += NT)
        s_a[j] = (j < m) ? __fdiv_rn(expf(s_sv[j] - M), Z1) : 0.f;
    float* src = s_a; float* dst = s_b;
    __syncthreads();
    for (int d = 1; d < NP; d <<= 1) {
        for (int j = tid; j < NP; j += NT)
            dst[j] = src[j] + ((j + d < NP) ? src[j + d] : 0.f);
        __syncthreads();
        float* t = src; src = dst; dst = t;
    }

    // top-p: keep cum (== suffix) > 1-p; rank 0 never masked
    const float c1 = 1.0f - p;
    int c = 0;
    for (int j = tid; j < m; j += NT) c += (src[j] > c1) ? 1 : 0;
    int m2 = blk_sumi(c, wi, tid); if (m2 < 1) m2 = 1;

    // min-p: keep exp(v-M) >= mp (argmax exp=1, always kept)
    int m3 = m2;
    if (mp > 0.f) {
        c = 0;
        for (int j = tid; j < m2; j += NT) c += (expf(s_sv[j] - M) >= mp) ? 1 : 0;
        m3 = blk_sumi(c, wi, tid); if (m3 < 1) m3 = 1;
    }

    // ------- final: argmax of exp(v-M)/max(noise,1e-10), min-index ties -------
    float bv = -1.f; int bi = 0x7FFFFFFF;
    for (int j = tid; j < m3; j += NT) {
        int ix = s_si[j];
        float sc = __fdiv_rn(expf(s_sv[j] - M), fmaxf(nz[ix], 1e-10f));
        if (sc > bv || (sc == bv && ix < bi)) { bv = sc; bi = ix; }
    }
    #pragma unroll
    for (int o = 16; o; o >>= 1) {
        float ov = __shfl_xor_sync(0xFFFFFFFFu, bv, o);
        int   oi = __shfl_xor_sync(0xFFFFFFFFu, bi, o);
        if (ov > bv || (ov == bv && oi < bi)) { bv = ov; bi = oi; }
    }
    if (lane == 0) { wf[tid >> 5] = bv; wi[tid >> 5] = bi; }
    __syncthreads();
    if (tid < 32) {
        float xv = (tid < NT / 32) ? wf[tid] : -1.f;
        int   xi = (tid < NT / 32) ? wi[tid] : 0x7FFFFFFF;
        #pragma unroll
        for (int o = 16; o; o >>= 1) {
            float ov = __shfl_xor_sync(0xFFFFFFFFu, xv, o);
            int   oi = __shfl_xor_sync(0xFFFFFFFFu, xi, o);
            if (ov > xv || (ov == xv && oi < xi)) { xv = ov; xi = oi; }
        }
        if (tid == 0) out[row] = (float)xi;
    }
}

extern "C" void kernel_launch(void* const* d_in, const int* in_sizes, int n_in,
                              void* d_out, int out_size)
{
    const float* logits = (const float*)d_in[0];
    const float* temps  = (const float*)d_in[1];
    const int*   topks  = (const int*)d_in[2];
    const float* topps  = (const float*)d_in[3];
    const float* minps  = (const float*)d_in[4];
    const float* noise  = (const float*)d_in[5];
    const int B = out_size;              // output: [B] sampled indices (float32)
    const int V = in_sizes[0] / B;       // logits: [B, V]

    const size_t smem = (size_t)NC * 8 + (size_t)SP * 8 + (size_t)SP * 8 + (size_t)HB * 4;
    cudaFuncSetAttribute(sampler_kernel,
                         cudaFuncAttributeMaxDynamicSharedMemorySize, (int)smem);
    sampler_kernel<<<B, NT, smem>>>(logits, temps, topks, topps, minps, noise,
                                    (float*)d_out, V);
}